// round 14
// baseline (speedup 1.0000x reference)
#include <cuda_runtime.h>
#include <cuda_bf16.h>
#include <math.h>
#include <stdint.h>

#define BB 16
#define NN 4096
#define MM 32
#define CC 512
#define MUVAL (1.0f/4096.0f)

__device__ float g_Kmat[BB*NN*MM];
__device__ float g_nu[BB*MM];
__device__ float g_sblk[2][256*MM];
__device__ float g_errblk2[2][4][256];
__device__ float g_otpart[2048];
__device__ __align__(256) __nv_bfloat16 g_xhi[BB*NN*CC];
__device__ __align__(256) __nv_bfloat16 g_xlo[BB*NN*CC];
__device__ __align__(256) __nv_bfloat16 g_phi[BB*NN*MM];
__device__ __align__(256) __nv_bfloat16 g_plo[BB*NN*MM];
__device__ __align__(256) __nv_bfloat16 g_wthi[CC*CC];     // [n][k]
__device__ __align__(256) __nv_bfloat16 g_wtlo[CC*CC];
__device__ __align__(256) __nv_bfloat16 g_y2thi[BB*CC*MM]; // [b][n][m]
__device__ __align__(256) __nv_bfloat16 g_y2tlo[BB*CC*MM];
__device__ unsigned g_bar1[16];
__device__ unsigned g_bar2;
__device__ unsigned g_bar_gen;
__device__ unsigned g_bbar[16];
__device__ unsigned g_bgen[16];

__device__ __forceinline__ uint32_t smem_u32(const void* p) {
    uint32_t a;
    asm("{ .reg .u64 t; cvta.to.shared.u64 t, %1; cvt.u32.u64 %0, t; }" : "=r"(a) : "l"(p));
    return a;
}
__device__ __forceinline__ void ldsm4(uint32_t* f, uint32_t addr) {
    asm volatile("ldmatrix.sync.aligned.m8n8.x4.shared.b16 {%0,%1,%2,%3}, [%4];"
        : "=r"(f[0]), "=r"(f[1]), "=r"(f[2]), "=r"(f[3]) : "r"(addr));
}
__device__ __forceinline__ void mma16816(float* c, const uint32_t* a, const uint32_t* b) {
    asm volatile("mma.sync.aligned.m16n8k16.row.col.f32.bf16.bf16.f32 "
        "{%0,%1,%2,%3}, {%4,%5,%6,%7}, {%8,%9}, {%0,%1,%2,%3};"
        : "+f"(c[0]), "+f"(c[1]), "+f"(c[2]), "+f"(c[3])
        : "r"(a[0]), "r"(a[1]), "r"(a[2]), "r"(a[3]), "r"(b[0]), "r"(b[1]));
}
__device__ __forceinline__ void cpa16(uint32_t dst, const void* src) {
    asm volatile("cp.async.cg.shared.global [%0], [%1], 16;" :: "r"(dst), "l"(src));
}
#define CP_COMMIT() asm volatile("cp.async.commit_group;" ::: "memory")
#define CP_WAIT(n)  asm volatile("cp.async.wait_group %0;" :: "n"(n) : "memory")

__device__ __forceinline__ void split_bf16(float v, __nv_bfloat16& h, __nv_bfloat16& l) {
    h = __float2bfloat16(v);
    l = __float2bfloat16(v - __bfloat162float(h));
}

__global__ void nuKernel(const float* __restrict__ score) {
    __shared__ int cnt[MM];
    int b = blockIdx.x, tid = threadIdx.x;
    if (tid < MM) cnt[tid] = 0;
    __syncthreads();
    const float* sb = score + (long)b * MM * NN;
    for (int p = tid; p < NN; p += 256) {
        float best = sb[p]; int bi = 0;
        #pragma unroll
        for (int k = 1; k < MM; ++k) {
            float v = sb[k*NN + p];
            if (v > best) { best = v; bi = k; }
        }
        atomicAdd(&cnt[bi], 1);
    }
    __syncthreads();
    if (tid < MM) {
        float t0 = (float)cnt[tid] / ((float)NN + 1e-8f) + 1e-6f;
        float s = t0;
        #pragma unroll
        for (int o = 16; o; o >>= 1) s += __shfl_xor_sync(0xffffffffu, s, o);
        g_nu[b*MM + tid] = t0 / s;
    }
}

// W1^T -> bf16 hi/lo [n][k]
__global__ void __launch_bounds__(256) wtKernel(const float* __restrict__ W) {
    __shared__ float t[32][33];
    int bx = blockIdx.x & 15, by = blockIdx.x >> 4;
    int tx = threadIdx.x & 31, ty = threadIdx.x >> 5;
    int k0 = by*32, n0 = bx*32;
    #pragma unroll
    for (int j = 0; j < 4; ++j)
        t[ty + 8*j][tx] = W[(long)(k0 + ty + 8*j)*CC + n0 + tx];
    __syncthreads();
    #pragma unroll
    for (int j = 0; j < 4; ++j) {
        int n = n0 + ty + 8*j, k = k0 + tx;
        __nv_bfloat16 h, l; split_bf16(t[tx][ty + 8*j], h, l);
        g_wthi[(long)n*CC + k] = h;
        g_wtlo[(long)n*CC + k] = l;
    }
}

// ---- fused convert(x->hi/lo) + K via HMMA. 512 CTAs (16 b x 32 rowblocks) ----
#define CPCH 80
__global__ void __launch_bounds__(256) costMMA(const float* __restrict__ x,
                                               const float* __restrict__ y) {
    __shared__ __align__(16) char sXH[128*CPCH];
    __shared__ __align__(16) char sXL[128*CPCH];
    __shared__ __align__(16) char sYH[32*CPCH];
    __shared__ __align__(16) char sYL[32*CPCH];
    __shared__ float yinvs[32], xinvs[128];
    uint32_t bXH = smem_u32(sXH), bXL = smem_u32(sXL);
    uint32_t bYH = smem_u32(sYH), bYL = smem_u32(sYL);
    int tid = threadIdx.x, lane = tid & 31, wid = tid >> 5;
    int b = blockIdx.x >> 5, rb = blockIdx.x & 31;
    int row0 = rb * 128;

    #pragma unroll
    for (int q = 0; q < 4; ++q) {
        int m = wid*4 + q;
        float ss = 0.f;
        #pragma unroll
        for (int j = 0; j < 16; ++j) { float vv = y[((long)b*MM + m)*CC + lane + j*32]; ss += vv*vv; }
        #pragma unroll
        for (int o = 16; o; o >>= 1) ss += __shfl_xor_sync(0xffffffffu, ss, o);
        if (lane == 0) yinvs[m] = rsqrtf(ss);
    }

    float acc[4][4];
    #pragma unroll
    for (int i = 0; i < 4; ++i)
        #pragma unroll
        for (int j = 0; j < 4; ++j) acc[i][j] = 0.f;
    float xn = 0.f;
    int r_ = tid >> 1, kq = tid & 1;

    for (int kc = 0; kc < CC; kc += 32) {
        __syncthreads();
        {
            long base = ((long)(b*NN + row0 + r_))*CC + kc + kq*16;
            const float4* xp = (const float4*)(x + base);
            #pragma unroll
            for (int j = 0; j < 4; ++j) {
                float4 v = xp[j];
                xn += v.x*v.x + v.y*v.y + v.z*v.z + v.w*v.w;
                __nv_bfloat16 h0,l0,h1,l1,h2,l2,h3,l3;
                split_bf16(v.x,h0,l0); split_bf16(v.y,h1,l1);
                split_bf16(v.z,h2,l2); split_bf16(v.w,h3,l3);
                __nv_bfloat162 hp0 = __halves2bfloat162(h0,h1), hp1 = __halves2bfloat162(h2,h3);
                __nv_bfloat162 lp0 = __halves2bfloat162(l0,l1), lp1 = __halves2bfloat162(l2,l3);
                long gidx = base + j*4;
                ((__nv_bfloat162*)(g_xhi + gidx))[0] = hp0; ((__nv_bfloat162*)(g_xhi + gidx))[1] = hp1;
                ((__nv_bfloat162*)(g_xlo + gidx))[0] = lp0; ((__nv_bfloat162*)(g_xlo + gidx))[1] = lp1;
                int so = r_*CPCH + kq*32 + j*8;
                *(__nv_bfloat162*)(sXH + so) = hp0; *(__nv_bfloat162*)(sXH + so + 4) = hp1;
                *(__nv_bfloat162*)(sXL + so) = lp0; *(__nv_bfloat162*)(sXL + so + 4) = lp1;
            }
        }
        {
            int m = tid >> 3, k4 = (tid & 7) * 4;
            float4 v = *(const float4*)(y + ((long)b*MM + m)*CC + kc + k4);
            __nv_bfloat16 h0,l0,h1,l1,h2,l2,h3,l3;
            split_bf16(v.x,h0,l0); split_bf16(v.y,h1,l1);
            split_bf16(v.z,h2,l2); split_bf16(v.w,h3,l3);
            int so = m*CPCH + k4*2;
            *(__nv_bfloat162*)(sYH + so)     = __halves2bfloat162(h0,h1);
            *(__nv_bfloat162*)(sYH + so + 4) = __halves2bfloat162(h2,h3);
            *(__nv_bfloat162*)(sYL + so)     = __halves2bfloat162(l0,l1);
            *(__nv_bfloat162*)(sYL + so + 4) = __halves2bfloat162(l2,l3);
        }
        __syncthreads();
        #pragma unroll
        for (int ks = 0; ks < 2; ++ks) {
            uint32_t ah[4], al[4], bh[2][4], bl[2][4];
            uint32_t aoff = (uint32_t)(wid*16 + (lane & 15))*CPCH + (uint32_t)(ks*16 + ((lane >> 4) << 3))*2;
            ldsm4(ah, bXH + aoff);
            ldsm4(al, bXL + aoff);
            #pragma unroll
            for (int p = 0; p < 2; ++p) {
                int row = p*16 + (lane & 7) + ((lane >> 4) & 1)*8;
                int col = ks*16 + (lane & 8);
                uint32_t boff = (uint32_t)row*CPCH + (uint32_t)col*2;
                ldsm4(bh[p], bYH + boff);
                ldsm4(bl[p], bYL + boff);
            }
            #pragma unroll
            for (int ni = 0; ni < 4; ++ni) {
                const uint32_t* bhp = &bh[ni >> 1][(ni & 1)*2];
                const uint32_t* blp = &bl[ni >> 1][(ni & 1)*2];
                mma16816(acc[ni], ah, bhp);
                mma16816(acc[ni], ah, blp);
                mma16816(acc[ni], al, bhp);
            }
        }
    }
    float xn2 = xn + __shfl_xor_sync(0xffffffffu, xn, 1);
    if ((tid & 1) == 0) xinvs[r_] = rsqrtf(xn2);
    __syncthreads();

    int gr = lane >> 2, gc = (lane & 3)*2;
    #pragma unroll
    for (int ni = 0; ni < 4; ++ni) {
        int m = ni*8 + gc;
        float ym0 = yinvs[m], ym1 = yinvs[m+1];
        #pragma unroll
        for (int h = 0; h < 2; ++h) {
            int r = wid*16 + gr + h*8;
            float xi = xinvs[r];
            float c0 = 1.f - acc[ni][h*2+0]*xi*ym0;
            float c1 = 1.f - acc[ni][h*2+1]*xi*ym1;
            long idx = ((long)(b*NN + row0 + r))*MM + m;
            *(float2*)(g_Kmat + idx) = make_float2(expf(-c0*20.f), expf(-c1*20.f));
        }
    }
}

// ---- sinkhorn: per-batch barrier per iter, global err every 4 iters; pi + ot fused ----
__device__ __forceinline__ void gbar() {
    __threadfence();
    __syncthreads();
    if (threadIdx.x == 0) {
        unsigned my = *(volatile unsigned*)&g_bar_gen;
        unsigned a = atomicAdd(&g_bar1[blockIdx.x >> 4], 1u) + 1u;
        if ((a & 15u) == 0u) {
            unsigned b2 = atomicAdd(&g_bar2, 1u) + 1u;
            if ((b2 & 15u) == 0u) atomicAdd(&g_bar_gen, 1u);
        }
        while (*(volatile unsigned*)&g_bar_gen == my) __nanosleep(32);
        __threadfence();
    }
    __syncthreads();
}
__device__ __forceinline__ void bbar(int batch) {
    __threadfence();
    __syncthreads();
    if (threadIdx.x == 0) {
        unsigned my = *(volatile unsigned*)&g_bgen[batch];
        if (atomicAdd(&g_bbar[batch], 1u) == 15u) {
            atomicExch(&g_bbar[batch], 0u);
            __threadfence();
            atomicAdd(&g_bgen[batch], 1u);
        } else {
            while (*(volatile unsigned*)&g_bgen[batch] == my) __nanosleep(32);
        }
        __threadfence();
    }
    __syncthreads();
}

__global__ void __launch_bounds__(256) sinkhornKernel(float* __restrict__ d_pi,
                                                      float* __restrict__ d_ot, int full) {
    __shared__ float ks[8*32*33];
    __shared__ float wacc[8][32];
    __shared__ float werr[8];
    __shared__ float dec[4];
    int tid = threadIdx.x, lane = tid & 31, wid = tid >> 5;
    int blk = blockIdx.x, gw = blk*8 + wid;
    int b = gw >> 7, chunk = gw & 127;
    long rowbase = (long)b*NN + chunk*32;
    float* kw = ks + wid*(32*33);
    for (int r = 0; r < 32; ++r)
        kw[r*33 + lane] = g_Kmat[(rowbase + r)*MM + lane];
    __syncwarp();

    float uprev = 0.f, vreg = 0.f;
    float usnap[4], vsnap[4];
    int done = 0;

    for (int g = 0; g < 13 && !done; ++g) {
        int len = (g == 12) ? 2 : 4;
        #pragma unroll
        for (int j = 0; j < 4; ++j) {
            if (j >= len) break;
            int it = g*4 + j;
            int buf = it & 1;
            float s = 0.f;
            #pragma unroll
            for (int m = 0; m < 32; ++m)
                s += kw[lane*33 + m] * __shfl_sync(0xffffffffu, vreg, m);
            float un = MUVAL / (s + 1e-8f);
            float errl = fabsf(un - uprev);
            uprev = un;
            float acc = 0.f;
            #pragma unroll
            for (int jj = 0; jj < 32; ++jj)
                acc += kw[jj*33 + lane] * __shfl_sync(0xffffffffu, un, jj);
            #pragma unroll
            for (int o = 16; o; o >>= 1) errl += __shfl_xor_sync(0xffffffffu, errl, o);
            wacc[wid][lane] = acc;
            if (lane == 0) werr[wid] = errl;
            __syncthreads();
            if (wid == 0) {
                float ba = wacc[0][lane]+wacc[1][lane]+wacc[2][lane]+wacc[3][lane]
                         + wacc[4][lane]+wacc[5][lane]+wacc[6][lane]+wacc[7][lane];
                __stcg(&g_sblk[buf][blk*32 + lane], ba);
                if (lane == 0)
                    __stcg(&g_errblk2[g & 1][j][blk],
                           werr[0]+werr[1]+werr[2]+werr[3]+werr[4]+werr[5]+werr[6]+werr[7]);
            }
            bbar(b);
            float ss = 0.f;
            #pragma unroll
            for (int q = 0; q < 16; ++q)
                ss += __ldcg(&g_sblk[buf][(b*16 + q)*32 + lane]);
            vreg = g_nu[b*MM + lane] / (ss + 1e-8f);
            usnap[j] = uprev;
            vsnap[j] = vreg;
        }
        gbar();
        if (tid < 4) dec[tid] = 1e30f;
        __syncthreads();
        if (wid < len) {
            float e = 0.f;
            #pragma unroll
            for (int q = 0; q < 8; ++q)
                e += __ldcg(&g_errblk2[g & 1][wid][lane + 32*q]);
            #pragma unroll
            for (int o = 16; o; o >>= 1) e += __shfl_xor_sync(0xffffffffu, e, o);
            if (lane == 0) dec[wid] = e;
        }
        __syncthreads();
        #pragma unroll
        for (int j = 0; j < 4; ++j) {
            if (!done && dec[j] < 1.6f) {
                uprev = usnap[j];
                vreg = vsnap[j];
                done = 1;
            }
        }
    }

    // fused pi / pinorm / ot epilogue (K in smem, u/v in regs)
    float ot = 0.f;
    for (int r = 0; r < 32; ++r) {
        float ur = __shfl_sync(0xffffffffu, uprev, r);
        float Kx = kw[r*33 + lane];
        float pi = ur * Kx * vreg;
        float rs = pi;
        #pragma unroll
        for (int o = 16; o; o >>= 1) rs += __shfl_xor_sync(0xffffffffu, rs, o);
        float pn = pi / (rs + 1e-8f);
        __nv_bfloat16 h, l; split_bf16(pn, h, l);
        long idx = (rowbase + r)*MM + lane;
        g_phi[idx] = h; g_plo[idx] = l;
        if (full) d_pi[idx] = pi;
        ot += pi * (-logf(Kx) * 0.05f);
    }
    #pragma unroll
    for (int o = 16; o; o >>= 1) ot += __shfl_xor_sync(0xffffffffu, ot, o);
    if (lane == 0) __stcg(&g_otpart[gw], ot);

    // ot reduction fused: one more tree barrier, then block 0 reduces
    gbar();
    if (full && blk == 0) {
        for (int bb2 = wid; bb2 < 16; bb2 += 8) {
            float s = __ldcg(&g_otpart[bb2*128 + lane]) + __ldcg(&g_otpart[bb2*128 + lane + 32])
                    + __ldcg(&g_otpart[bb2*128 + lane + 64]) + __ldcg(&g_otpart[bb2*128 + lane + 96]);
            #pragma unroll
            for (int o = 16; o; o >>= 1) s += __shfl_xor_sync(0xffffffffu, s, o);
            if (lane == 0) d_ot[bb2] = s;
        }
    }
}

// Y2^T -> bf16 hi/lo [b][n][m]
__global__ void __launch_bounds__(256) y2Kernel(const float* __restrict__ y,
                                                const float* __restrict__ W) {
    __shared__ float ys[MM][64];
    int tid = threadIdx.x;
    int b = blockIdx.x >> 2, c0 = (blockIdx.x & 3) * 128;
    int col = c0 + (tid & 127), mh = tid >> 7;
    const float* W2 = W + 512*512;
    float acc[16];
    #pragma unroll
    for (int i = 0; i < 16; ++i) acc[i] = 0.f;
    for (int kc = 0; kc < CC; kc += 64) {
        __syncthreads();
        {
            int m = tid >> 3, k4 = (tid & 7) * 8;
            *(float4*)&ys[m][k4]     = *(const float4*)(y + ((long)b*MM + m)*CC + kc + k4);
            *(float4*)&ys[m][k4 + 4] = *(const float4*)(y + ((long)b*MM + m)*CC + kc + k4 + 4);
        }
        __syncthreads();
        #pragma unroll 4
        for (int k = 0; k < 64; ++k) {
            float w = W2[(long)(kc + k)*CC + col];
            #pragma unroll
            for (int i = 0; i < 16; ++i) acc[i] += ys[mh*16 + i][k] * w;
        }
    }
    #pragma unroll
    for (int i = 0; i < 16; ++i) {
        __nv_bfloat16 h, l; split_bf16(acc[i], h, l);
        long idx = ((long)b*CC + col)*MM + mh*16 + i;
        g_y2thi[idx] = h;
        g_y2tlo[idx] = l;
    }
}

// ---- HMMA GEMM: CTA 128x256, warp 64x64, K=32 chunks, 2 stages. 1024 CTAs ----
#define GP 80
#define GALO 10240
#define GBHI 20480
#define GBLO 40960
#define GSTAGE 61440
#define GSMEM (2*GSTAGE)

__global__ void __launch_bounds__(256, 1) gemmMMA(const float* __restrict__ bias,
                                                  float* __restrict__ out) {
    extern __shared__ char sm[];
    uint32_t sb = smem_u32(sm);
    int tid = threadIdx.x, lane = tid & 31, wid = tid >> 5;
    int rowTile = blockIdx.x >> 1, colTile = blockIdx.x & 1;
    int row0 = rowTile*128, n0 = colTile*256;
    int b = rowTile >> 5;
    int wr0 = (wid & 1)*64, wn0 = (wid >> 1)*64;

    float acc[4][8][4];
    #pragma unroll
    for (int i = 0; i < 4; ++i)
        #pragma unroll
        for (int j = 0; j < 8; ++j)
            #pragma unroll
            for (int q = 0; q < 4; ++q) acc[i][j][q] = 0.f;

    auto loadChunk = [&](int c, uint32_t dst) {
        #pragma unroll
        for (int i = 0; i < 12; ++i) {
            int s = tid + i*256;
            uint32_t dso;
            const char* src;
            if (s < 1024) {        // A: 2 halves x 128 rows x 4 chunks of 16B
                int half = s >> 9, r = (s >> 2) & 127, k16 = s & 3;
                dso = (uint32_t)half*GALO + (uint32_t)r*GP + (uint32_t)k16*16;
                if (c < 16)
                    src = (const char*)(half ? g_xlo : g_xhi) + ((long)(row0 + r)*CC + c*32)*2 + k16*16;
                else
                    src = (const char*)(half ? g_plo : g_phi) + (long)(row0 + r)*64 + k16*16;
            } else {               // B: 2 halves x 256 rows x 4 chunks
                int s2 = s - 1024;
                int half = s2 >> 10, n = (s2 >> 2) & 255, k16 = s2 & 3;
                dso = (uint32_t)GBHI + (uint32_t)half*20480 + (uint32_t)n*GP + (uint32_t)k16*16;
                if (c < 16)
                    src = (const char*)(half ? g_wtlo : g_wthi) + ((long)(n0 + n)*CC + c*32)*2 + k16*16;
                else
                    src = (const char*)(half ? g_y2tlo : g_y2thi) + ((long)b*CC + n0 + n)*64 + k16*16;
            }
            cpa16(dst + dso, src);
        }
        CP_COMMIT();
    };

    loadChunk(0, sb);
    for (int c = 0; c < 17; ++c) {
        if (c < 16) {
            loadChunk(c + 1, sb + ((c + 1) & 1)*GSTAGE);
            CP_WAIT(1);
        } else {
            CP_WAIT(0);
        }
        __syncthreads();
        uint32_t s0 = sb + (c & 1)*GSTAGE;
        #pragma unroll
        for (int ks = 0; ks < 2; ++ks) {
            uint32_t ah[4][4], al[4][4];
            #pragma unroll
            for (int mi = 0; mi < 4; ++mi) {
                uint32_t aoff = (uint32_t)(wr0 + mi*16 + (lane & 15))*GP + (uint32_t)(ks*16 + ((lane >> 4) << 3))*2;
                ldsm4(ah[mi], s0 + aoff);
                ldsm4(al[mi], s0 + GALO + aoff);
            }
            #pragma unroll
            for (int p = 0; p < 4; ++p) {
                uint32_t bh[4], bl[4];
                int row = wn0 + p*16 + (lane & 7) + ((lane >> 4) & 1)*8;
                int col = ks*16 + (lane & 8);
                uint32_t boff = (uint32_t)row*GP + (uint32_t)col*2;
                ldsm4(bh, s0 + GBHI + boff);
                ldsm4(bl, s0 + GBLO + boff);
                #pragma unroll
                for (int mi = 0; mi < 4; ++mi) {
                    #pragma unroll
                    for (int t = 0; t < 2; ++t) {
                        float* a = acc[mi][p*2 + t];
                        mma16816(a, ah[mi], &bh[t*2]);
                        mma16816(a, ah[mi], &bl[t*2]);
                        mma16816(a, al[mi], &bh[t*2]);
                    }
                }
            }
        }
        __syncthreads();
    }

    int gr = lane >> 2, gc = (lane & 3)*2;
    #pragma unroll
    for (int mi = 0; mi < 4; ++mi)
        #pragma unroll
        for (int ni = 0; ni < 8; ++ni) {
            int col = n0 + wn0 + ni*8 + gc;
            float b0 = bias[col], b1 = bias[col+1];
            long ro0 = (long)(row0 + wr0 + mi*16 + gr)*CC + col;
            long ro1 = ro0 + 8*CC;
            float2 o0 = { acc[mi][ni][0] + b0, acc[mi][ni][1] + b1 };
            float2 o1 = { acc[mi][ni][2] + b0, acc[mi][ni][3] + b1 };
            *(float2*)(out + ro0) = o0;
            *(float2*)(out + ro1) = o1;
        }
}

// LayerNorm in-place
__global__ void __launch_bounds__(256) lnKernel(float* __restrict__ out,
                                                const float* __restrict__ gamma,
                                                const float* __restrict__ beta) {
    int tid = threadIdx.x, lane = tid & 31, wid = tid >> 5;
    long row = (long)blockIdx.x * 8 + wid;
    float4* rp = (float4*)(out + row * CC);
    float4 v[4];
    float sum = 0.f;
    #pragma unroll
    for (int j = 0; j < 4; ++j) {
        v[j] = rp[lane + j*32];
        sum += v[j].x + v[j].y + v[j].z + v[j].w;
    }
    #pragma unroll
    for (int o = 16; o; o >>= 1) sum += __shfl_xor_sync(0xffffffffu, sum, o);
    float mean = sum * (1.0f/512.0f);
    float var = 0.f;
    #pragma unroll
    for (int j = 0; j < 4; ++j) {
        float dx = v[j].x - mean, dy = v[j].y - mean, dz = v[j].z - mean, dw = v[j].w - mean;
        var += dx*dx + dy*dy + dz*dz + dw*dw;
    }
    #pragma unroll
    for (int o = 16; o; o >>= 1) var += __shfl_xor_sync(0xffffffffu, var, o);
    float rs = rsqrtf(var * (1.0f/512.0f) + 1e-5f);
    const float4* g4 = (const float4*)gamma;
    const float4* b4 = (const float4*)beta;
    #pragma unroll
    for (int j = 0; j < 4; ++j) {
        float4 g = g4[lane + j*32], bt = b4[lane + j*32];
        float4 o;
        o.x = (v[j].x - mean)*rs*g.x + bt.x;
        o.y = (v[j].y - mean)*rs*g.y + bt.y;
        o.z = (v[j].z - mean)*rs*g.z + bt.z;
        o.w = (v[j].w - mean)*rs*g.w + bt.w;
        rp[lane + j*32] = o;
    }
}

extern "C" void kernel_launch(void* const* d_in, const int* in_sizes, int n_in,
                              void* d_out, int out_size) {
    const float* x     = (const float*)d_in[0];
    const float* y     = (const float*)d_in[1];
    const float* score = (const float*)d_in[2];
    const float* W     = (const float*)d_in[3];
    const float* bias  = (const float*)d_in[4];
    const float* gamma = (const float*)d_in[5];
    const float* beta  = (const float*)d_in[6];
    float* out = (float*)d_out;

    const long OUT_ELEMS = (long)BB*NN*CC;
    int full = (out_size >= (int)(OUT_ELEMS + BB + (long)BB*NN*MM));
    float* d_ot = full ? out + OUT_ELEMS : nullptr;
    float* d_pi = full ? out + OUT_ELEMS + BB : nullptr;

    static cudaStream_t s2 = 0;
    static cudaEvent_t evRoot = 0, evNu = 0, evSide = 0;
    if (!s2) {
        cudaStreamCreateWithFlags(&s2, cudaStreamNonBlocking);
        cudaEventCreateWithFlags(&evRoot, cudaEventDisableTiming);
        cudaEventCreateWithFlags(&evNu, cudaEventDisableTiming);
        cudaEventCreateWithFlags(&evSide, cudaEventDisableTiming);
        cudaFuncSetAttribute(gemmMMA, cudaFuncAttributeMaxDynamicSharedMemorySize, GSMEM);
    }

    cudaEventRecord(evRoot, 0);
    cudaStreamWaitEvent(s2, evRoot, 0);
    nuKernel<<<BB, 256, 0, s2>>>(score);
    cudaEventRecord(evNu, s2);
    wtKernel<<<256, 256, 0, s2>>>(W);
    y2Kernel<<<64, 256, 0, s2>>>(y, W);
    cudaEventRecord(evSide, s2);

    costMMA<<<512, 256>>>(x, y);
    cudaStreamWaitEvent(0, evNu, 0);
    sinkhornKernel<<<256, 256>>>(d_pi, d_ot, full);
    cudaStreamWaitEvent(0, evSide, 0);
    gemmMMA<<<1024, 256, GSMEM>>>(bias, out);
    lnKernel<<<8192, 256>>>(out, gamma, beta);
}

// round 16
// speedup vs baseline: 1.0236x; 1.0236x over previous
#include <cuda_runtime.h>
#include <cuda_bf16.h>
#include <math.h>
#include <stdint.h>

#define BB 16
#define NN 4096
#define MM 32
#define CC 512
#define MUVAL (1.0f/4096.0f)

__device__ float g_Kmat[BB*NN*MM];
__device__ float g_nu[BB*MM];
__device__ float g_sblk[2][256*MM];
__device__ float g_errblk2[2][4][256];
__device__ float g_otpart[2048];
__device__ __align__(256) __nv_bfloat16 g_xhi[BB*NN*CC];
__device__ __align__(256) __nv_bfloat16 g_xlo[BB*NN*CC];
__device__ __align__(256) __nv_bfloat16 g_phi[BB*NN*MM];
__device__ __align__(256) __nv_bfloat16 g_plo[BB*NN*MM];
__device__ __align__(256) __nv_bfloat16 g_wthi[CC*CC];     // [n][k]
__device__ __align__(256) __nv_bfloat16 g_wtlo[CC*CC];
__device__ __align__(256) __nv_bfloat16 g_y2thi[BB*CC*MM]; // [b][n][m]
__device__ __align__(256) __nv_bfloat16 g_y2tlo[BB*CC*MM];
__device__ unsigned g_bar1[16];
__device__ unsigned g_bar2;
__device__ unsigned g_bar_gen;
__device__ unsigned g_bbar[16];
__device__ unsigned g_bgen[16];

__device__ __forceinline__ uint32_t smem_u32(const void* p) {
    uint32_t a;
    asm("{ .reg .u64 t; cvta.to.shared.u64 t, %1; cvt.u32.u64 %0, t; }" : "=r"(a) : "l"(p));
    return a;
}
__device__ __forceinline__ void ldsm4(uint32_t* f, uint32_t addr) {
    asm volatile("ldmatrix.sync.aligned.m8n8.x4.shared.b16 {%0,%1,%2,%3}, [%4];"
        : "=r"(f[0]), "=r"(f[1]), "=r"(f[2]), "=r"(f[3]) : "r"(addr));
}
__device__ __forceinline__ void mma16816(float* c, const uint32_t* a, const uint32_t* b) {
    asm volatile("mma.sync.aligned.m16n8k16.row.col.f32.bf16.bf16.f32 "
        "{%0,%1,%2,%3}, {%4,%5,%6,%7}, {%8,%9}, {%0,%1,%2,%3};"
        : "+f"(c[0]), "+f"(c[1]), "+f"(c[2]), "+f"(c[3])
        : "r"(a[0]), "r"(a[1]), "r"(a[2]), "r"(a[3]), "r"(b[0]), "r"(b[1]));
}
__device__ __forceinline__ void cpa16(uint32_t dst, const void* src) {
    asm volatile("cp.async.cg.shared.global [%0], [%1], 16;" :: "r"(dst), "l"(src));
}
#define CP_COMMIT() asm volatile("cp.async.commit_group;" ::: "memory")
#define CP_WAIT(n)  asm volatile("cp.async.wait_group %0;" :: "n"(n) : "memory")

__device__ __forceinline__ void split_bf16(float v, __nv_bfloat16& h, __nv_bfloat16& l) {
    h = __float2bfloat16(v);
    l = __float2bfloat16(v - __bfloat162float(h));
}

__global__ void nuKernel(const float* __restrict__ score) {
    __shared__ int cnt[MM];
    int b = blockIdx.x, tid = threadIdx.x;
    if (tid < MM) cnt[tid] = 0;
    __syncthreads();
    const float* sb = score + (long)b * MM * NN;
    for (int p = tid; p < NN; p += 256) {
        float best = sb[p]; int bi = 0;
        #pragma unroll
        for (int k = 1; k < MM; ++k) {
            float v = sb[k*NN + p];
            if (v > best) { best = v; bi = k; }
        }
        atomicAdd(&cnt[bi], 1);
    }
    __syncthreads();
    if (tid < MM) {
        float t0 = (float)cnt[tid] / ((float)NN + 1e-8f) + 1e-6f;
        float s = t0;
        #pragma unroll
        for (int o = 16; o; o >>= 1) s += __shfl_xor_sync(0xffffffffu, s, o);
        g_nu[b*MM + tid] = t0 / s;
    }
}

// W1^T -> bf16 hi/lo [n][k]
__global__ void __launch_bounds__(256) wtKernel(const float* __restrict__ W) {
    __shared__ float t[32][33];
    int bx = blockIdx.x & 15, by = blockIdx.x >> 4;
    int tx = threadIdx.x & 31, ty = threadIdx.x >> 5;
    int k0 = by*32, n0 = bx*32;
    #pragma unroll
    for (int j = 0; j < 4; ++j)
        t[ty + 8*j][tx] = W[(long)(k0 + ty + 8*j)*CC + n0 + tx];
    __syncthreads();
    #pragma unroll
    for (int j = 0; j < 4; ++j) {
        int n = n0 + ty + 8*j, k = k0 + tx;
        __nv_bfloat16 h, l; split_bf16(t[tx][ty + 8*j], h, l);
        g_wthi[(long)n*CC + k] = h;
        g_wtlo[(long)n*CC + k] = l;
    }
}

// ---- fused convert(x->hi/lo) + K via HMMA. 512 CTAs (16 b x 32 rowblocks) ----
#define CPCH 80
__global__ void __launch_bounds__(256) costMMA(const float* __restrict__ x,
                                               const float* __restrict__ y) {
    __shared__ __align__(16) char sXH[128*CPCH];
    __shared__ __align__(16) char sXL[128*CPCH];
    __shared__ __align__(16) char sYH[32*CPCH];
    __shared__ __align__(16) char sYL[32*CPCH];
    __shared__ float yinvs[32], xinvs[128];
    uint32_t bXH = smem_u32(sXH), bXL = smem_u32(sXL);
    uint32_t bYH = smem_u32(sYH), bYL = smem_u32(sYL);
    int tid = threadIdx.x, lane = tid & 31, wid = tid >> 5;
    int b = blockIdx.x >> 5, rb = blockIdx.x & 31;
    int row0 = rb * 128;

    #pragma unroll
    for (int q = 0; q < 4; ++q) {
        int m = wid*4 + q;
        float ss = 0.f;
        #pragma unroll
        for (int j = 0; j < 16; ++j) { float vv = y[((long)b*MM + m)*CC + lane + j*32]; ss += vv*vv; }
        #pragma unroll
        for (int o = 16; o; o >>= 1) ss += __shfl_xor_sync(0xffffffffu, ss, o);
        if (lane == 0) yinvs[m] = rsqrtf(ss);
    }

    float acc[4][4];
    #pragma unroll
    for (int i = 0; i < 4; ++i)
        #pragma unroll
        for (int j = 0; j < 4; ++j) acc[i][j] = 0.f;
    float xn = 0.f;
    int r_ = tid >> 1, kq = tid & 1;

    for (int kc = 0; kc < CC; kc += 32) {
        __syncthreads();
        {
            long base = ((long)(b*NN + row0 + r_))*CC + kc + kq*16;
            const float4* xp = (const float4*)(x + base);
            #pragma unroll
            for (int j = 0; j < 4; ++j) {
                float4 v = xp[j];
                xn += v.x*v.x + v.y*v.y + v.z*v.z + v.w*v.w;
                __nv_bfloat16 h0,l0,h1,l1,h2,l2,h3,l3;
                split_bf16(v.x,h0,l0); split_bf16(v.y,h1,l1);
                split_bf16(v.z,h2,l2); split_bf16(v.w,h3,l3);
                __nv_bfloat162 hp0 = __halves2bfloat162(h0,h1), hp1 = __halves2bfloat162(h2,h3);
                __nv_bfloat162 lp0 = __halves2bfloat162(l0,l1), lp1 = __halves2bfloat162(l2,l3);
                long gidx = base + j*4;
                ((__nv_bfloat162*)(g_xhi + gidx))[0] = hp0; ((__nv_bfloat162*)(g_xhi + gidx))[1] = hp1;
                ((__nv_bfloat162*)(g_xlo + gidx))[0] = lp0; ((__nv_bfloat162*)(g_xlo + gidx))[1] = lp1;
                int so = r_*CPCH + kq*32 + j*8;
                *(__nv_bfloat162*)(sXH + so) = hp0; *(__nv_bfloat162*)(sXH + so + 4) = hp1;
                *(__nv_bfloat162*)(sXL + so) = lp0; *(__nv_bfloat162*)(sXL + so + 4) = lp1;
            }
        }
        {
            int m = tid >> 3, k4 = (tid & 7) * 4;
            float4 v = *(const float4*)(y + ((long)b*MM + m)*CC + kc + k4);
            __nv_bfloat16 h0,l0,h1,l1,h2,l2,h3,l3;
            split_bf16(v.x,h0,l0); split_bf16(v.y,h1,l1);
            split_bf16(v.z,h2,l2); split_bf16(v.w,h3,l3);
            int so = m*CPCH + k4*2;
            *(__nv_bfloat162*)(sYH + so)     = __halves2bfloat162(h0,h1);
            *(__nv_bfloat162*)(sYH + so + 4) = __halves2bfloat162(h2,h3);
            *(__nv_bfloat162*)(sYL + so)     = __halves2bfloat162(l0,l1);
            *(__nv_bfloat162*)(sYL + so + 4) = __halves2bfloat162(l2,l3);
        }
        __syncthreads();
        #pragma unroll
        for (int ks = 0; ks < 2; ++ks) {
            uint32_t ah[4], al[4], bh[2][4], bl[2][4];
            uint32_t aoff = (uint32_t)(wid*16 + (lane & 15))*CPCH + (uint32_t)(ks*16 + ((lane >> 4) << 3))*2;
            ldsm4(ah, bXH + aoff);
            ldsm4(al, bXL + aoff);
            #pragma unroll
            for (int p = 0; p < 2; ++p) {
                int row = p*16 + (lane & 7) + ((lane >> 4) & 1)*8;
                int col = ks*16 + (lane & 8);
                uint32_t boff = (uint32_t)row*CPCH + (uint32_t)col*2;
                ldsm4(bh[p], bYH + boff);
                ldsm4(bl[p], bYL + boff);
            }
            #pragma unroll
            for (int ni = 0; ni < 4; ++ni) {
                const uint32_t* bhp = &bh[ni >> 1][(ni & 1)*2];
                const uint32_t* blp = &bl[ni >> 1][(ni & 1)*2];
                mma16816(acc[ni], ah, bhp);
                mma16816(acc[ni], ah, blp);
                mma16816(acc[ni], al, bhp);
            }
        }
    }
    float xn2 = xn + __shfl_xor_sync(0xffffffffu, xn, 1);
    if ((tid & 1) == 0) xinvs[r_] = rsqrtf(xn2);
    __syncthreads();

    int gr = lane >> 2, gc = (lane & 3)*2;
    #pragma unroll
    for (int ni = 0; ni < 4; ++ni) {
        int m = ni*8 + gc;
        float ym0 = yinvs[m], ym1 = yinvs[m+1];
        #pragma unroll
        for (int h = 0; h < 2; ++h) {
            int r = wid*16 + gr + h*8;
            float xi = xinvs[r];
            float c0 = 1.f - acc[ni][h*2+0]*xi*ym0;
            float c1 = 1.f - acc[ni][h*2+1]*xi*ym1;
            long idx = ((long)(b*NN + row0 + r))*MM + m;
            *(float2*)(g_Kmat + idx) = make_float2(expf(-c0*20.f), expf(-c1*20.f));
        }
    }
}

// ---- sinkhorn: per-batch barrier per iter, global err every 4 iters; pi + ot fused ----
__device__ __forceinline__ void gbar() {
    __threadfence();
    __syncthreads();
    if (threadIdx.x == 0) {
        unsigned my = *(volatile unsigned*)&g_bar_gen;
        unsigned a = atomicAdd(&g_bar1[blockIdx.x >> 4], 1u) + 1u;
        if ((a & 15u) == 0u) {
            unsigned b2 = atomicAdd(&g_bar2, 1u) + 1u;
            if ((b2 & 15u) == 0u) atomicAdd(&g_bar_gen, 1u);
        }
        while (*(volatile unsigned*)&g_bar_gen == my) __nanosleep(32);
        __threadfence();
    }
    __syncthreads();
}
__device__ __forceinline__ void bbar(int batch) {
    __threadfence();
    __syncthreads();
    if (threadIdx.x == 0) {
        unsigned my = *(volatile unsigned*)&g_bgen[batch];
        if (atomicAdd(&g_bbar[batch], 1u) == 15u) {
            atomicExch(&g_bbar[batch], 0u);
            __threadfence();
            atomicAdd(&g_bgen[batch], 1u);
        } else {
            while (*(volatile unsigned*)&g_bgen[batch] == my) __nanosleep(32);
        }
        __threadfence();
    }
    __syncthreads();
}

__global__ void __launch_bounds__(256) sinkhornKernel(float* __restrict__ d_pi,
                                                      float* __restrict__ d_ot, int full) {
    __shared__ float ks[8*32*33];
    __shared__ float wacc[8][32];
    __shared__ float werr[8];
    __shared__ float dec[4];
    int tid = threadIdx.x, lane = tid & 31, wid = tid >> 5;
    int blk = blockIdx.x, gw = blk*8 + wid;
    int b = gw >> 7, chunk = gw & 127;
    long rowbase = (long)b*NN + chunk*32;
    float* kw = ks + wid*(32*33);
    for (int r = 0; r < 32; ++r)
        kw[r*33 + lane] = g_Kmat[(rowbase + r)*MM + lane];
    __syncwarp();

    float uprev = 0.f, vreg = 0.f;
    float usnap[4], vsnap[4];
    int done = 0;

    for (int g = 0; g < 13 && !done; ++g) {
        int len = (g == 12) ? 2 : 4;
        #pragma unroll
        for (int j = 0; j < 4; ++j) {
            if (j >= len) break;
            int it = g*4 + j;
            int buf = it & 1;
            float s = 0.f;
            #pragma unroll
            for (int m = 0; m < 32; ++m)
                s += kw[lane*33 + m] * __shfl_sync(0xffffffffu, vreg, m);
            float un = MUVAL / (s + 1e-8f);
            float errl = fabsf(un - uprev);
            uprev = un;
            float acc = 0.f;
            #pragma unroll
            for (int jj = 0; jj < 32; ++jj)
                acc += kw[jj*33 + lane] * __shfl_sync(0xffffffffu, un, jj);
            #pragma unroll
            for (int o = 16; o; o >>= 1) errl += __shfl_xor_sync(0xffffffffu, errl, o);
            wacc[wid][lane] = acc;
            if (lane == 0) werr[wid] = errl;
            __syncthreads();
            if (wid == 0) {
                float ba = wacc[0][lane]+wacc[1][lane]+wacc[2][lane]+wacc[3][lane]
                         + wacc[4][lane]+wacc[5][lane]+wacc[6][lane]+wacc[7][lane];
                __stcg(&g_sblk[buf][blk*32 + lane], ba);
                if (lane == 0)
                    __stcg(&g_errblk2[g & 1][j][blk],
                           werr[0]+werr[1]+werr[2]+werr[3]+werr[4]+werr[5]+werr[6]+werr[7]);
            }
            bbar(b);
            float ss = 0.f;
            #pragma unroll
            for (int q = 0; q < 16; ++q)
                ss += __ldcg(&g_sblk[buf][(b*16 + q)*32 + lane]);
            vreg = g_nu[b*MM + lane] / (ss + 1e-8f);
            usnap[j] = uprev;
            vsnap[j] = vreg;
        }
        gbar();
        if (tid < 4) dec[tid] = 1e30f;
        __syncthreads();
        if (wid < len) {
            float e = 0.f;
            #pragma unroll
            for (int q = 0; q < 8; ++q)
                e += __ldcg(&g_errblk2[g & 1][wid][lane + 32*q]);
            #pragma unroll
            for (int o = 16; o; o >>= 1) e += __shfl_xor_sync(0xffffffffu, e, o);
            if (lane == 0) dec[wid] = e;
        }
        __syncthreads();
        #pragma unroll
        for (int j = 0; j < 4; ++j) {
            if (!done && dec[j] < 1.6f) {
                uprev = usnap[j];
                vreg = vsnap[j];
                done = 1;
            }
        }
    }

    // fused pi / pinorm / ot epilogue (K in smem, u/v in regs)
    float ot = 0.f;
    for (int r = 0; r < 32; ++r) {
        float ur = __shfl_sync(0xffffffffu, uprev, r);
        float Kx = kw[r*33 + lane];
        float pi = ur * Kx * vreg;
        float rs = pi;
        #pragma unroll
        for (int o = 16; o; o >>= 1) rs += __shfl_xor_sync(0xffffffffu, rs, o);
        float pn = pi / (rs + 1e-8f);
        __nv_bfloat16 h, l; split_bf16(pn, h, l);
        long idx = (rowbase + r)*MM + lane;
        g_phi[idx] = h; g_plo[idx] = l;
        if (full) d_pi[idx] = pi;
        ot += pi * (-logf(Kx) * 0.05f);
    }
    #pragma unroll
    for (int o = 16; o; o >>= 1) ot += __shfl_xor_sync(0xffffffffu, ot, o);
    if (lane == 0) __stcg(&g_otpart[gw], ot);

    // ot reduction fused: one more tree barrier, then block 0 reduces
    gbar();
    if (full && blk == 0) {
        for (int bb2 = wid; bb2 < 16; bb2 += 8) {
            float s = __ldcg(&g_otpart[bb2*128 + lane]) + __ldcg(&g_otpart[bb2*128 + lane + 32])
                    + __ldcg(&g_otpart[bb2*128 + lane + 64]) + __ldcg(&g_otpart[bb2*128 + lane + 96]);
            #pragma unroll
            for (int o = 16; o; o >>= 1) s += __shfl_xor_sync(0xffffffffu, s, o);
            if (lane == 0) d_ot[bb2] = s;
        }
    }
}

// Y2^T -> bf16 hi/lo [b][n][m]
__global__ void __launch_bounds__(256) y2Kernel(const float* __restrict__ y,
                                                const float* __restrict__ W) {
    __shared__ float ys[MM][64];
    int tid = threadIdx.x;
    int b = blockIdx.x >> 2, c0 = (blockIdx.x & 3) * 128;
    int col = c0 + (tid & 127), mh = tid >> 7;
    const float* W2 = W + 512*512;
    float acc[16];
    #pragma unroll
    for (int i = 0; i < 16; ++i) acc[i] = 0.f;
    for (int kc = 0; kc < CC; kc += 64) {
        __syncthreads();
        {
            int m = tid >> 3, k4 = (tid & 7) * 8;
            *(float4*)&ys[m][k4]     = *(const float4*)(y + ((long)b*MM + m)*CC + kc + k4);
            *(float4*)&ys[m][k4 + 4] = *(const float4*)(y + ((long)b*MM + m)*CC + kc + k4 + 4);
        }
        __syncthreads();
        #pragma unroll 4
        for (int k = 0; k < 64; ++k) {
            float w = W2[(long)(kc + k)*CC + col];
            #pragma unroll
            for (int i = 0; i < 16; ++i) acc[i] += ys[mh*16 + i][k] * w;
        }
    }
    #pragma unroll
    for (int i = 0; i < 16; ++i) {
        __nv_bfloat16 h, l; split_bf16(acc[i], h, l);
        long idx = ((long)b*CC + col)*MM + mh*16 + i;
        g_y2thi[idx] = h;
        g_y2tlo[idx] = l;
    }
}

// ---- HMMA GEMM, K=32 chunks, 2 stages (2 CTAs/SM). 2048 CTAs ----
#define GP 80
#define GA_LO 10240
#define GB_HI 20480
#define GB_LO 30720
#define GSTAGE 40960
#define GSMEM (2*GSTAGE)

__device__ __forceinline__ void gemmCompute(uint32_t sbase, int wr0, int wn0, int lane,
                                            float acc[4][4][4]) {
    #pragma unroll
    for (int ks = 0; ks < 2; ++ks) {
        uint32_t ah[4][4], al[4][4];
        #pragma unroll
        for (int mi = 0; mi < 4; ++mi) {
            uint32_t aoff = (uint32_t)(wr0 + mi*16 + (lane & 15))*GP + (uint32_t)(ks*16 + ((lane >> 4) << 3))*2;
            ldsm4(ah[mi], sbase + aoff);
            ldsm4(al[mi], sbase + GA_LO + aoff);
        }
        uint32_t bh[2][4], bl[2][4];
        #pragma unroll
        for (int p = 0; p < 2; ++p) {
            int row = wn0 + p*16 + (lane & 7) + ((lane >> 4) & 1)*8;
            int col = ks*16 + (lane & 8);
            uint32_t boff = (uint32_t)row*GP + (uint32_t)col*2;
            ldsm4(bh[p], sbase + GB_HI + boff);
            ldsm4(bl[p], sbase + GB_LO + boff);
        }
        #pragma unroll
        for (int mi = 0; mi < 4; ++mi)
            #pragma unroll
            for (int ni = 0; ni < 4; ++ni) {
                const uint32_t* bhp = &bh[ni >> 1][(ni & 1)*2];
                const uint32_t* blp = &bl[ni >> 1][(ni & 1)*2];
                mma16816(acc[mi][ni], ah[mi], bhp);
                mma16816(acc[mi][ni], ah[mi], blp);
                mma16816(acc[mi][ni], al[mi], bhp);
            }
    }
}

__global__ void __launch_bounds__(256, 2) gemmMMA(const float* __restrict__ bias,
                                                  float* __restrict__ out) {
    extern __shared__ char sm[];
    uint32_t sb = smem_u32(sm);
    int tid = threadIdx.x, lane = tid & 31, wid = tid >> 5;
    int rowTile = blockIdx.x >> 2, colTile = blockIdx.x & 3;
    int row0 = rowTile*128, n0 = colTile*128;
    int b = rowTile >> 5;
    int wr0 = (wid >> 2)*64, wn0 = (wid & 3)*32;

    float acc[4][4][4];
    #pragma unroll
    for (int i = 0; i < 4; ++i)
        #pragma unroll
        for (int j = 0; j < 4; ++j)
            #pragma unroll
            for (int q = 0; q < 4; ++q) acc[i][j][q] = 0.f;

    auto loadChunk = [&](int c, uint32_t dst) {
        #pragma unroll
        for (int i = 0; i < 2; ++i) {
            int u = tid + i*256, r = u >> 2, k16 = u & 3;
            uint32_t so = (uint32_t)r*GP + (uint32_t)k16*16;
            if (c < 16) {
                long ga = ((long)(row0 + r)*CC + c*32)*2 + k16*16;
                long gb = ((long)(n0   + r)*CC + c*32)*2 + k16*16;
                cpa16(dst + so,         (const char*)g_xhi  + ga);
                cpa16(dst + GA_LO + so, (const char*)g_xlo  + ga);
                cpa16(dst + GB_HI + so, (const char*)g_wthi + gb);
                cpa16(dst + GB_LO + so, (const char*)g_wtlo + gb);
            } else {
                long ga = (long)(row0 + r)*64 + k16*16;
                long gb = ((long)b*CC + n0 + r)*64 + k16*16;
                cpa16(dst + so,         (const char*)g_phi   + ga);
                cpa16(dst + GA_LO + so, (const char*)g_plo   + ga);
                cpa16(dst + GB_HI + so, (const char*)g_y2thi + gb);
                cpa16(dst + GB_LO + so, (const char*)g_y2tlo + gb);
            }
        }
        CP_COMMIT();
    };

    loadChunk(0, sb);
    for (int c = 0; c < 17; ++c) {
        if (c < 16) {
            loadChunk(c + 1, sb + ((c + 1) & 1)*GSTAGE);
            CP_WAIT(1);
        } else {
            CP_WAIT(0);
        }
        __syncthreads();
        gemmCompute(sb + (c & 1)*GSTAGE, wr0, wn0, lane, acc);
        __syncthreads();
    }

    int gr = lane >> 2, gc = (lane & 3)*2;
    #pragma unroll
    for (int mi = 0; mi < 4; ++mi)
        #pragma unroll
        for (int ni = 0; ni < 4; ++ni) {
            int col = n0 + wn0 + ni*8 + gc;
            float b0 = bias[col], b1 = bias[col+1];
            long ro0 = (long)(row0 + wr0 + mi*16 + gr)*CC + col;
            long ro1 = ro0 + 8*CC;
            float2 o0 = { acc[mi][ni][0] + b0, acc[mi][ni][1] + b1 };
            float2 o1 = { acc[mi][ni][2] + b0, acc[mi][ni][3] + b1 };
            *(float2*)(out + ro0) = o0;
            *(float2*)(out + ro1) = o1;
        }
}

// LayerNorm in-place
__global__ void __launch_bounds__(256) lnKernel(float* __restrict__ out,
                                                const float* __restrict__ gamma,
                                                const float* __restrict__ beta) {
    int tid = threadIdx.x, lane = tid & 31, wid = tid >> 5;
    long row = (long)blockIdx.x * 8 + wid;
    float4* rp = (float4*)(out + row * CC);
    float4 v[4];
    float sum = 0.f;
    #pragma unroll
    for (int j = 0; j < 4; ++j) {
        v[j] = rp[lane + j*32];
        sum += v[j].x + v[j].y + v[j].z + v[j].w;
    }
    #pragma unroll
    for (int o = 16; o; o >>= 1) sum += __shfl_xor_sync(0xffffffffu, sum, o);
    float mean = sum * (1.0f/512.0f);
    float var = 0.f;
    #pragma unroll
    for (int j = 0; j < 4; ++j) {
        float dx = v[j].x - mean, dy = v[j].y - mean, dz = v[j].z - mean, dw = v[j].w - mean;
        var += dx*dx + dy*dy + dz*dz + dw*dw;
    }
    #pragma unroll
    for (int o = 16; o; o >>= 1) var += __shfl_xor_sync(0xffffffffu, var, o);
    float rs = rsqrtf(var * (1.0f/512.0f) + 1e-5f);
    const float4* g4 = (const float4*)gamma;
    const float4* b4 = (const float4*)beta;
    #pragma unroll
    for (int j = 0; j < 4; ++j) {
        float4 g = g4[lane + j*32], bt = b4[lane + j*32];
        float4 o;
        o.x = (v[j].x - mean)*rs*g.x + bt.x;
        o.y = (v[j].y - mean)*rs*g.y + bt.y;
        o.z = (v[j].z - mean)*rs*g.z + bt.z;
        o.w = (v[j].w - mean)*rs*g.w + bt.w;
        rp[lane + j*32] = o;
    }
}

extern "C" void kernel_launch(void* const* d_in, const int* in_sizes, int n_in,
                              void* d_out, int out_size) {
    const float* x     = (const float*)d_in[0];
    const float* y     = (const float*)d_in[1];
    const float* score = (const float*)d_in[2];
    const float* W     = (const float*)d_in[3];
    const float* bias  = (const float*)d_in[4];
    const float* gamma = (const float*)d_in[5];
    const float* beta  = (const float*)d_in[6];
    float* out = (float*)d_out;

    const long OUT_ELEMS = (long)BB*NN*CC;
    int full = (out_size >= (int)(OUT_ELEMS + BB + (long)BB*NN*MM));
    float* d_ot = full ? out + OUT_ELEMS : nullptr;
    float* d_pi = full ? out + OUT_ELEMS + BB : nullptr;

    static cudaStream_t s2 = 0;
    static cudaEvent_t evRoot = 0, evNu = 0, evSide = 0;
    if (!s2) {
        cudaStreamCreateWithFlags(&s2, cudaStreamNonBlocking);
        cudaEventCreateWithFlags(&evRoot, cudaEventDisableTiming);
        cudaEventCreateWithFlags(&evNu, cudaEventDisableTiming);
        cudaEventCreateWithFlags(&evSide, cudaEventDisableTiming);
        cudaFuncSetAttribute(gemmMMA, cudaFuncAttributeMaxDynamicSharedMemorySize, GSMEM);
    }

    cudaEventRecord(evRoot, 0);
    cudaStreamWaitEvent(s2, evRoot, 0);
    nuKernel<<<BB, 256, 0, s2>>>(score);
    cudaEventRecord(evNu, s2);
    wtKernel<<<256, 256, 0, s2>>>(W);
    y2Kernel<<<64, 256, 0, s2>>>(y, W);
    cudaEventRecord(evSide, s2);

    costMMA<<<512, 256>>>(x, y);
    cudaStreamWaitEvent(0, evNu, 0);
    sinkhornKernel<<<256, 256>>>(d_pi, d_ot, full);
    cudaStreamWaitEvent(0, evSide, 0);
    gemmMMA<<<2048, 256, GSMEM>>>(bias, out);
    lnKernel<<<8192, 256>>>(out, gamma, beta);
}